// round 12
// baseline (speedup 1.0000x reference)
#include <cuda_runtime.h>
#include <cuda_bf16.h>
#include <math.h>
#include <stdint.h>

#define D_MODEL  1024
#define N_HEAD   16
#define HEAD_DIM 64
#define B_SZ     2
#define T_SEQ    2048
#define M_ROWS   (B_SZ * T_SEQ)   // 4096
#define K3       3072             // split K: 3 terms of 1024

// ---------------- scratch (device globals: allocation-free) ----------------
// rope cos/sin table: [t][d] for t<2048, d<32
__device__ float2 g_rope[T_SEQ * 32];

// GEMM split buffers (K'=3072)
__device__ __nv_bfloat16 g_xs  [M_ROWS * K3];
__device__ __nv_bfloat16 g_zs  [M_ROWS * K3];   // written directly by attn
__device__ __nv_bfloat16 g_wqs [D_MODEL * K3];
__device__ __nv_bfloat16 g_wks [D_MODEL * K3];
__device__ __nv_bfloat16 g_wq2s[D_MODEL * K3];
__device__ __nv_bfloat16 g_wk2s[D_MODEL * K3];
__device__ __nv_bfloat16 g_wvs [D_MODEL * K3];
__device__ __nv_bfloat16 g_wps [D_MODEL * K3];

// attention split buffers (post-rope, written by gemm5 epilogue), [b*T, 1024]
__device__ __nv_bfloat16 g_qh [M_ROWS * D_MODEL];
__device__ __nv_bfloat16 g_ql [M_ROWS * D_MODEL];
__device__ __nv_bfloat16 g_q2h[M_ROWS * D_MODEL];
__device__ __nv_bfloat16 g_q2l[M_ROWS * D_MODEL];
__device__ __nv_bfloat16 g_kh [M_ROWS * D_MODEL];
__device__ __nv_bfloat16 g_kl [M_ROWS * D_MODEL];
__device__ __nv_bfloat16 g_k2h[M_ROWS * D_MODEL];
__device__ __nv_bfloat16 g_k2l[M_ROWS * D_MODEL];
// V transposed split: [b, h, d, t]
__device__ __nv_bfloat16 g_vh [B_SZ * N_HEAD * HEAD_DIM * T_SEQ];
__device__ __nv_bfloat16 g_vl [B_SZ * N_HEAD * HEAD_DIM * T_SEQ];

// ======================= helpers ===========================================
__device__ __forceinline__ uint32_t smem_u32(const void* p) {
    uint32_t a;
    asm("{ .reg .u64 t; cvta.to.shared.u64 t, %1; cvt.u32.u64 %0, t; }"
        : "=r"(a) : "l"(p));
    return a;
}
#define SWZ(off) ((off) ^ (((off) >> 3) & 0x70))

__device__ __forceinline__ void ldsm_x4(uint32_t addr, uint32_t& r0, uint32_t& r1,
                                        uint32_t& r2, uint32_t& r3) {
    asm volatile("ldmatrix.sync.aligned.m8n8.x4.shared.b16 {%0,%1,%2,%3}, [%4];"
                 : "=r"(r0), "=r"(r1), "=r"(r2), "=r"(r3) : "r"(addr));
}
__device__ __forceinline__ void mma16816(float& d0, float& d1, float& d2, float& d3,
                                         uint32_t a0, uint32_t a1, uint32_t a2, uint32_t a3,
                                         uint32_t b0, uint32_t b1) {
    asm volatile(
        "mma.sync.aligned.m16n8k16.row.col.f32.bf16.bf16.f32 "
        "{%0,%1,%2,%3}, {%4,%5,%6,%7}, {%8,%9}, {%0,%1,%2,%3};"
        : "+f"(d0), "+f"(d1), "+f"(d2), "+f"(d3)
        : "r"(a0), "r"(a1), "r"(a2), "r"(a3), "r"(b0), "r"(b1));
}
__device__ __forceinline__ void bsplit(float x, unsigned short& h, unsigned short& lo) {
    __nv_bfloat16 hh = __float2bfloat16(x);
    __nv_bfloat16 ll = __float2bfloat16(x - __bfloat162float(hh));
    h  = __bfloat16_as_ushort(hh);
    lo = __bfloat16_as_ushort(ll);
}
__device__ __forceinline__ void bsplit2(float x0, float x1, uint32_t& hw, uint32_t& lw) {
    unsigned short h0, l0, h1, l1;
    bsplit(x0, h0, l0);
    bsplit(x1, h1, l1);
    hw = (uint32_t)h0 | ((uint32_t)h1 << 16);
    lw = (uint32_t)l0 | ((uint32_t)l1 << 16);
}
#define CPA16(dst, src) \
    asm volatile("cp.async.cg.shared.global [%0], [%1], 16;" :: "r"(dst), "l"(src))
#define CPA_COMMIT() asm volatile("cp.async.commit_group;" ::: "memory")
#define CPA_WAIT0()  asm volatile("cp.async.wait_group 0;" ::: "memory")

// ======================= split fp32 -> bf16 3-term =========================
__device__ __forceinline__ void split_body(const float* __restrict__ X,
                                           __nv_bfloat16* __restrict__ S,
                                           int idx, int mode) {
    float4 v = ((const float4*)X)[idx];
    int r  = idx >> 8;
    int cq = (idx & 255) * 4;
    float vv[4] = {v.x, v.y, v.z, v.w};
    __nv_bfloat16 h[4], l[4];
#pragma unroll
    for (int j = 0; j < 4; j++) {
        h[j] = __float2bfloat16(vv[j]);
        l[j] = __float2bfloat16(vv[j] - __bfloat162float(h[j]));
    }
    size_t base = (size_t)r * K3 + cq;
    uint64_t hw = *(uint64_t*)h, lw = *(uint64_t*)l;
    *(uint64_t*)&S[base] = hw;
    if (mode == 0) {                       // A: hi, lo, hi
        *(uint64_t*)&S[base + 1024] = lw;
        *(uint64_t*)&S[base + 2048] = hw;
    } else {                               // W: hi, hi, lo
        *(uint64_t*)&S[base + 1024] = hw;
        *(uint64_t*)&S[base + 2048] = lw;
    }
}

__global__ void split_kernel(const float* __restrict__ X,
                             __nv_bfloat16* __restrict__ S, int n4, int mode) {
    int idx = blockIdx.x * blockDim.x + threadIdx.x;
    if (idx >= n4) return;
    split_body(X, S, idx, mode);
}

__global__ void split_w6(const float* __restrict__ W0, const float* __restrict__ W1,
                         const float* __restrict__ W2, const float* __restrict__ W3,
                         const float* __restrict__ W4, const float* __restrict__ W5,
                         __nv_bfloat16* __restrict__ S0, __nv_bfloat16* __restrict__ S1,
                         __nv_bfloat16* __restrict__ S2, __nv_bfloat16* __restrict__ S3,
                         __nv_bfloat16* __restrict__ S4, __nv_bfloat16* __restrict__ S5,
                         int n4) {
    int idx = blockIdx.x * blockDim.x + threadIdx.x;
    if (idx >= n4) return;
    const float* Ws[6] = {W0, W1, W2, W3, W4, W5};
    __nv_bfloat16* Ss[6] = {S0, S1, S2, S3, S4, S5};
    split_body(Ws[blockIdx.y], Ss[blockIdx.y], idx, 1);
}

// ======================= HMMA GEMM mainloop ================================
// 4-stage pipeline, one barrier per chunk (proof in round-11 notes).
#define TILE_BYTES 16384
#define STAGE_BYTES (2 * TILE_BYTES)
#define NSTAGE 4
#define GEMM_SMEM (NSTAGE * STAGE_BYTES + 1024)   // 132 KB (>= 128*129*4 stage)
#define NCHUNK (K3 / 64)                 // 48
#define SMW 129                          // fp32 epilogue staging row stride

__device__ __forceinline__ void gemm_load(const __nv_bfloat16* __restrict__ As,
                                          const __nv_bfloat16* __restrict__ Ws,
                                          int m0, int n0, int c, uint32_t stb, int tid)
{
#pragma unroll
    for (int it = 0; it < 8; ++it) {
        int op = tid + it * 256;
        int t  = op >> 10;
        int r  = (op >> 3) & 127;
        int s  = op & 7;
        const __nv_bfloat16* g =
            (t ? Ws + (size_t)(n0 + r) * K3 : As + (size_t)(m0 + r) * K3)
            + c * 64 + s * 8;
        uint32_t d = stb + t * TILE_BYTES + SWZ(r * 128 + s * 16);
        CPA16(d, g);
    }
}

__device__ __forceinline__ void gemm_mainloop(const __nv_bfloat16* __restrict__ As,
                                              const __nv_bfloat16* __restrict__ Ws,
                                              int m0, int n0, uint32_t sb,
                                              float acc[4][4][4])
{
    const int tid = threadIdx.x;
    const int wid = tid >> 5;
    const int l   = tid & 31;
    const int mw  = wid >> 2;
    const int nw  = wid & 3;

#pragma unroll
    for (int i = 0; i < 4; i++)
#pragma unroll
        for (int j = 0; j < 4; j++)
#pragma unroll
            for (int e = 0; e < 4; e++) acc[i][j][e] = 0.0f;

    const int a_row = mw * 64 + (l & 15);
    const int a_byt = (l >> 4) << 4;
    const int b_row = nw * 32 + ((l >> 4) << 3) + (l & 7);
    const int b_byt = ((l >> 3) & 1) << 4;

    gemm_load(As, Ws, m0, n0, 0, sb, tid);
    CPA_COMMIT();
    gemm_load(As, Ws, m0, n0, 1, sb + STAGE_BYTES, tid);
    CPA_COMMIT();

    for (int c = 0; c < NCHUNK; ++c) {
        if (c + 2 < NCHUNK) {
            gemm_load(As, Ws, m0, n0, c + 2, sb + ((c + 2) % NSTAGE) * STAGE_BYTES, tid);
            CPA_COMMIT();
            asm volatile("cp.async.wait_group 2;" ::: "memory");
        } else if (c + 2 == NCHUNK) {
            asm volatile("cp.async.wait_group 1;" ::: "memory");
        } else {
            CPA_WAIT0();
        }
        __syncthreads();

        const uint32_t aT = sb + (c % NSTAGE) * STAGE_BYTES;
        const uint32_t bT = aT + TILE_BYTES;

#pragma unroll
        for (int ks = 0; ks < 4; ++ks) {
            uint32_t a[4][4], b[4][2];
#pragma unroll
            for (int mi = 0; mi < 4; ++mi) {
                uint32_t ad = aT + SWZ((a_row + mi * 16) * 128 + ks * 32 + a_byt);
                ldsm_x4(ad, a[mi][0], a[mi][1], a[mi][2], a[mi][3]);
            }
#pragma unroll
            for (int nb = 0; nb < 2; ++nb) {
                uint32_t bd = bT + SWZ((b_row + nb * 16) * 128 + ks * 32 + b_byt);
                ldsm_x4(bd, b[nb * 2][0], b[nb * 2][1], b[nb * 2 + 1][0], b[nb * 2 + 1][1]);
            }
#pragma unroll
            for (int mi = 0; mi < 4; ++mi)
#pragma unroll
                for (int nj = 0; nj < 4; ++nj)
                    mma16816(acc[mi][nj][0], acc[mi][nj][1], acc[mi][nj][2], acc[mi][nj][3],
                             a[mi][0], a[mi][1], a[mi][2], a[mi][3],
                             b[nj][0], b[nj][1]);
        }
    }
}

// plain fp32-output GEMM (final projection)
__global__ void __launch_bounds__(256) gemm_hmma(
    const __nv_bfloat16* __restrict__ As,
    const __nv_bfloat16* __restrict__ Ws,
    float* __restrict__ C)
{
    extern __shared__ char gsm_raw[];
    uint32_t sb = (smem_u32(gsm_raw) + 1023u) & ~1023u;
    const int tid = threadIdx.x;
    const int wid = tid >> 5;
    const int l   = tid & 31;
    const int mw  = wid >> 2;
    const int nw  = wid & 3;
    const int m0  = blockIdx.y * 128;
    const int n0  = blockIdx.x * 128;

    float acc[4][4][4];
    gemm_mainloop(As, Ws, m0, n0, sb, acc);

    const int er = l >> 2;
    const int ec = (l & 3) * 2;
#pragma unroll
    for (int mi = 0; mi < 4; ++mi) {
        int mrow = m0 + mw * 64 + mi * 16 + er;
#pragma unroll
        for (int nj = 0; nj < 4; ++nj) {
            int ncol = n0 + nw * 32 + nj * 8 + ec;
            *(float2*)&C[(size_t)mrow * 1024 + ncol] =
                make_float2(acc[mi][nj][0], acc[mi][nj][1]);
            *(float2*)&C[(size_t)(mrow + 8) * 1024 + ncol] =
                make_float2(acc[mi][nj][2], acc[mi][nj][3]);
        }
    }
}

// batched projections with FUSED epilogue:
//   zi 0..3 (q,k,q2,k2): rope + hi/lo bf16 split, written to (OH,OL)
//   zi 4    (v):         transpose to [b,h,d,t] + hi/lo split -> (vh,vl)
__global__ void __launch_bounds__(256) gemm_hmma5(
    const __nv_bfloat16* __restrict__ As,
    const __nv_bfloat16* __restrict__ W0, const __nv_bfloat16* __restrict__ W1,
    const __nv_bfloat16* __restrict__ W2, const __nv_bfloat16* __restrict__ W3,
    const __nv_bfloat16* __restrict__ W4,
    const float2* __restrict__ tab,
    __nv_bfloat16* __restrict__ QH,  __nv_bfloat16* __restrict__ QL,
    __nv_bfloat16* __restrict__ KHo, __nv_bfloat16* __restrict__ KLo,
    __nv_bfloat16* __restrict__ Q2H, __nv_bfloat16* __restrict__ Q2L,
    __nv_bfloat16* __restrict__ K2Ho,__nv_bfloat16* __restrict__ K2Lo,
    __nv_bfloat16* __restrict__ VHo, __nv_bfloat16* __restrict__ VLo)
{
    extern __shared__ char gsm_raw[];
    char* ap = (char*)(((uintptr_t)gsm_raw + 1023) & ~(uintptr_t)1023);
    uint32_t sb = (smem_u32(gsm_raw) + 1023u) & ~1023u;

    const int tid = threadIdx.x;
    const int wid = tid >> 5;
    const int l   = tid & 31;
    const int mw  = wid >> 2;
    const int nw  = wid & 3;
    const int m0  = blockIdx.y * 128;
    const int n0  = blockIdx.x * 128;
    const int zi  = blockIdx.z;

    const __nv_bfloat16* Ws[5] = {W0, W1, W2, W3, W4};

    float acc[4][4][4];
    gemm_mainloop(As, Ws[zi], m0, n0, sb, acc);

    // ---- fused epilogue: stage fp32 tile in smem ----
    __syncthreads();                       // mainloop readers done with smem
    float* smf = (float*)ap;
    const int er = l >> 2;
    const int ec = (l & 3) * 2;
#pragma unroll
    for (int mi = 0; mi < 4; ++mi) {
        int r = mw * 64 + mi * 16 + er;
#pragma unroll
        for (int nj = 0; nj < 4; ++nj) {
            int cc = nw * 32 + nj * 8 + ec;
            smf[r * SMW + cc]           = acc[mi][nj][0];
            smf[r * SMW + cc + 1]       = acc[mi][nj][1];
            smf[(r + 8) * SMW + cc]     = acc[mi][nj][2];
            smf[(r + 8) * SMW + cc + 1] = acc[mi][nj][3];
        }
    }
    __syncthreads();

    if (zi < 4) {
        __nv_bfloat16* OH = (zi == 0) ? QH : (zi == 1) ? KHo : (zi == 2) ? Q2H : K2Ho;
        __nv_bfloat16* OL = (zi == 0) ? QL : (zi == 1) ? KLo : (zi == 2) ? Q2L : K2Lo;
#pragma unroll 4
        for (int it = 0; it < 32; ++it) {
            int idx = tid + it * 256;      // 0..8191 : (row, pair)
            int r  = idx >> 6;             // 0..127
            int pc = idx & 63;             // 0..63
            int c  = pc + (pc & 32);       // {0..31} u {64..95}
            float y1 = smf[r * SMW + c];
            float y2 = smf[r * SMW + c + 32];
            int m = m0 + r;
            float2 cs = tab[(m & (T_SEQ - 1)) * 32 + (c & 31)];
            float ny1 =  y1 * cs.x + y2 * cs.y;
            float ny2 = -y1 * cs.y + y2 * cs.x;
            unsigned short h1, l1, h2, l2;
            bsplit(ny1, h1, l1);
            bsplit(ny2, h2, l2);
            size_t o = (size_t)m * D_MODEL + n0 + c;
            OH[o]      = __ushort_as_bfloat16(h1);
            OL[o]      = __ushort_as_bfloat16(l1);
            OH[o + 32] = __ushort_as_bfloat16(h2);
            OL[o + 32] = __ushort_as_bfloat16(l2);
        }
    } else {
#pragma unroll 4
        for (int it = 0; it < 64; ++it) {
            int idx = tid + it * 256;      // 0..16383
            int rr = idx & 127;            // row within tile (t-fast)
            int c  = idx >> 7;             // 0..127 col
            float x = smf[rr * SMW + c];
            int m   = m0 + rr;
            int col = n0 + c;
            size_t o = ((size_t)(((m >> 11) * N_HEAD + (col >> 6)) * HEAD_DIM
                                 + (col & 63))) * T_SEQ + (m & (T_SEQ - 1));
            unsigned short hh, ll;
            bsplit(x, hh, ll);
            VHo[o] = __ushort_as_bfloat16(hh);
            VLo[o] = __ushort_as_bfloat16(ll);
        }
    }
}

// ---------------- rope table: 65536 threads, double trig once --------------
__global__ void rope_table_kernel(float2* __restrict__ tab) {
    int idx = blockIdx.x * blockDim.x + threadIdx.x;   // t*32 + d
    if (idx >= T_SEQ * 32) return;
    int t = idx >> 5;
    int d = idx & 31;
    double inv = exp(-(double)d * 0.28782313662425572);   // ln(10000)/32
    double ang = (double)t * inv;
    tab[idx] = make_float2((float)cos(ang), (float)sin(ang));
}

// ---------------- HMMA flash-style attention (register repack) -------------
// 3-stage K/V pipeline, ONE barrier per kt:
//   iter kt: issue load(kt+1) into stage (kt+1)%3 -> wait_group 1 -> sync -> compute(kt)
// Overwrite safety: stage (kt+1)%3 last read at compute(kt-2); all warps
// passed sync(kt-1) only after finishing compute(kt-2).
#define AQ_TILE 16384
#define ST_BASE 65536
#define ST_SIZE 49152
#define ST_VOFF 32768
#define AT_NST  3
#define AT_SMEM (ST_BASE + AT_NST * ST_SIZE)   // 212992

__device__ __forceinline__ void attn_load_kv(
    const __nv_bfloat16* __restrict__ kh,  const __nv_bfloat16* __restrict__ kl,
    const __nv_bfloat16* __restrict__ k2h, const __nv_bfloat16* __restrict__ k2l,
    const __nv_bfloat16* __restrict__ vh,  const __nv_bfloat16* __restrict__ vl,
    int b, int h, int kt, uint32_t stb, int tid)
{
    const __nv_bfloat16* ksrc[4] = {kh, kl, k2h, k2l};
#pragma unroll
    for (int it = 0; it < 8; ++it) {
        int op = tid + it * 256;
        int arr = op >> 9;
        int r   = (op >> 3) & 63;
        int s   = op & 7;
        const __nv_bfloat16* g =
            ksrc[arr] + ((size_t)(b * T_SEQ + kt * 64 + r)) * D_MODEL + h * HEAD_DIM + s * 8;
        CPA16(stb + arr * 8192 + SWZ(r * 128 + s * 16), g);
    }
#pragma unroll
    for (int it = 0; it < 4; ++it) {
        int op = tid + it * 256;
        int arr = op >> 9;
        int r   = (op >> 3) & 63;
        int s   = op & 7;
        const __nv_bfloat16* g =
            (arr ? vl : vh)
            + ((size_t)((b * N_HEAD + h) * HEAD_DIM + r)) * T_SEQ + kt * 64 + s * 8;
        CPA16(stb + ST_VOFF + arr * 8192 + SWZ(r * 128 + s * 16), g);
    }
}

__global__ void __launch_bounds__(256, 1) attn_hmma(
    const __nv_bfloat16* __restrict__ qh,  const __nv_bfloat16* __restrict__ ql,
    const __nv_bfloat16* __restrict__ q2h, const __nv_bfloat16* __restrict__ q2l,
    const __nv_bfloat16* __restrict__ kh,  const __nv_bfloat16* __restrict__ kl,
    const __nv_bfloat16* __restrict__ k2h, const __nv_bfloat16* __restrict__ k2l,
    const __nv_bfloat16* __restrict__ vh,  const __nv_bfloat16* __restrict__ vl,
    __nv_bfloat16* __restrict__ zs)
{
    extern __shared__ char atn_raw[];
    const uint32_t sb = smem_u32(atn_raw);

    const int qt = (int)gridDim.x - 1 - (int)blockIdx.x;   // heavy first
    const int h  = blockIdx.y;
    const int b  = blockIdx.z;
    const int tid = threadIdx.x;
    const int wid = tid >> 5;
    const int l   = tid & 31;

    const int qrow0 = qt * 128;

    const int a_row = wid * 16 + (l & 15);
    const int a_byt = (l >> 4) << 4;
    const int b_row = ((l >> 4) << 3) + (l & 7);
    const int b_byt = ((l >> 3) & 1) << 4;
    const int er = l >> 2;
    const int ec = (l & 3) * 2;
    const int grow0 = qrow0 + wid * 16 + er;

    // ---- Q tiles ----
    {
        const __nv_bfloat16* src[4] = {qh, ql, q2h, q2l};
#pragma unroll
        for (int it = 0; it < 16; ++it) {
            int op = tid + it * 256;
            int arr = op >> 10;
            int r   = (op >> 3) & 127;
            int s   = op & 7;
            const __nv_bfloat16* g =
                src[arr] + ((size_t)(b * T_SEQ + qrow0 + r)) * D_MODEL + h * HEAD_DIM + s * 8;
            CPA16(sb + arr * AQ_TILE + SWZ(r * 128 + s * 16), g);
        }
        CPA_COMMIT();
    }
    attn_load_kv(kh, kl, k2h, k2l, vh, vl, b, h, 0, sb + ST_BASE, tid);
    CPA_COMMIT();

    float acc[8][4];
#pragma unroll
    for (int i = 0; i < 8; i++)
#pragma unroll
        for (int e = 0; e < 4; e++) acc[i][e] = 0.0f;

    const float scl = 1.0f / 4096.0f;
    const int kt_max = 2 * qt + 1;

    for (int kt = 0; kt <= kt_max; ++kt) {
        const uint32_t stb = sb + ST_BASE + (kt % AT_NST) * ST_SIZE;

        if (kt < kt_max) {
            attn_load_kv(kh, kl, k2h, k2l, vh, vl, b, h, kt + 1,
                         sb + ST_BASE + ((kt + 1) % AT_NST) * ST_SIZE, tid);
            CPA_COMMIT();
            asm volatile("cp.async.wait_group 1;" ::: "memory");
        } else {
            CPA_WAIT0();
        }
        __syncthreads();

        if (kt * 64 > qrow0 + wid * 16 + 15) continue;

        const uint32_t KH = stb, KL = stb + 8192, K2H = stb + 16384, K2L = stb + 24576;
        const uint32_t VH = stb + ST_VOFF, VL = stb + ST_VOFF + 8192;

        float s1[8][4], s2[8][4];
#pragma unroll
        for (int i = 0; i < 8; i++)
#pragma unroll
            for (int e = 0; e < 4; e++) { s1[i][e] = 0.0f; s2[i][e] = 0.0f; }

#pragma unroll
        for (int ks = 0; ks < 4; ++ks) {
            uint32_t aH[4], aL[4], bH[8][2], bL[8][2];
            ldsm_x4(sb + 0 * AQ_TILE + SWZ(a_row * 128 + ks * 32 + a_byt), aH[0], aH[1], aH[2], aH[3]);
            ldsm_x4(sb + 1 * AQ_TILE + SWZ(a_row * 128 + ks * 32 + a_byt), aL[0], aL[1], aL[2], aL[3]);
#pragma unroll
            for (int g = 0; g < 4; ++g) {
                ldsm_x4(KH + SWZ((b_row + g * 16) * 128 + ks * 32 + b_byt),
                        bH[g * 2][0], bH[g * 2][1], bH[g * 2 + 1][0], bH[g * 2 + 1][1]);
                ldsm_x4(KL + SWZ((b_row + g * 16) * 128 + ks * 32 + b_byt),
                        bL[g * 2][0], bL[g * 2][1], bL[g * 2 + 1][0], bL[g * 2 + 1][1]);
            }
#pragma unroll
            for (int nb = 0; nb < 8; ++nb) {
                mma16816(s1[nb][0], s1[nb][1], s1[nb][2], s1[nb][3],
                         aH[0], aH[1], aH[2], aH[3], bH[nb][0], bH[nb][1]);
                mma16816(s1[nb][0], s1[nb][1], s1[nb][2], s1[nb][3],
                         aL[0], aL[1], aL[2], aL[3], bH[nb][0], bH[nb][1]);
                mma16816(s1[nb][0], s1[nb][1], s1[nb][2], s1[nb][3],
                         aH[0], aH[1], aH[2], aH[3], bL[nb][0], bL[nb][1]);
            }
        }
#pragma unroll
        for (int ks = 0; ks < 4; ++ks) {
            uint32_t aH[4], aL[4], bH[8][2], bL[8][2];
            ldsm_x4(sb + 2 * AQ_TILE + SWZ(a_row * 128 + ks * 32 + a_byt), aH[0], aH[1], aH[2], aH[3]);
            ldsm_x4(sb + 3 * AQ_TILE + SWZ(a_row * 128 + ks * 32 + a_byt), aL[0], aL[1], aL[2], aL[3]);
#pragma unroll
            for (int g = 0; g < 4; ++g) {
                ldsm_x4(K2H + SWZ((b_row + g * 16) * 128 + ks * 32 + b_byt),
                        bH[g * 2][0], bH[g * 2][1], bH[g * 2 + 1][0], bH[g * 2 + 1][1]);
                ldsm_x4(K2L + SWZ((b_row + g * 16) * 128 + ks * 32 + b_byt),
                        bL[g * 2][0], bL[g * 2][1], bL[g * 2 + 1][0], bL[g * 2 + 1][1]);
            }
#pragma unroll
            for (int nb = 0; nb < 8; ++nb) {
                mma16816(s2[nb][0], s2[nb][1], s2[nb][2], s2[nb][3],
                         aH[0], aH[1], aH[2], aH[3], bH[nb][0], bH[nb][1]);
                mma16816(s2[nb][0], s2[nb][1], s2[nb][2], s2[nb][3],
                         aL[0], aL[1], aL[2], aL[3], bH[nb][0], bH[nb][1]);
                mma16816(s2[nb][0], s2[nb][1], s2[nb][2], s2[nb][3],
                         aH[0], aH[1], aH[2], aH[3], bL[nb][0], bL[nb][1]);
            }
        }

        const bool maskt = (kt >= 2 * qt);
        uint32_t pH[8], pL[8], pH2[8], pL2[8];
#pragma unroll
        for (int nb = 0; nb < 8; ++nb) {
            float p0 = s1[nb][0] * s2[nb][0] * scl;
            float p1 = s1[nb][1] * s2[nb][1] * scl;
            float p2 = s1[nb][2] * s2[nb][2] * scl;
            float p3 = s1[nb][3] * s2[nb][3] * scl;
            if (maskt) {
                int c0 = kt * 64 + nb * 8 + ec;
                if (c0     > grow0    ) p0 = 0.0f;
                if (c0 + 1 > grow0    ) p1 = 0.0f;
                if (c0     > grow0 + 8) p2 = 0.0f;
                if (c0 + 1 > grow0 + 8) p3 = 0.0f;
            }
            bsplit2(p0, p1, pH[nb],  pL[nb]);
            bsplit2(p2, p3, pH2[nb], pL2[nb]);
        }

#pragma unroll
        for (int kc = 0; kc < 4; ++kc) {
            uint32_t aPH[4] = {pH[2 * kc], pH2[2 * kc], pH[2 * kc + 1], pH2[2 * kc + 1]};
            uint32_t aPL[4] = {pL[2 * kc], pL2[2 * kc], pL[2 * kc + 1], pL2[2 * kc + 1]};
            uint32_t bH[8][2], bL[8][2];
#pragma unroll
            for (int g = 0; g < 4; ++g) {
                ldsm_x4(VH + SWZ((b_row + g * 16) * 128 + kc * 32 + b_byt),
                        bH[g * 2][0], bH[g * 2][1], bH[g * 2 + 1][0], bH[g * 2 + 1][1]);
                ldsm_x4(VL + SWZ((b_row + g * 16) * 128 + kc * 32 + b_byt),
                        bL[g * 2][0], bL[g * 2][1], bL[g * 2 + 1][0], bL[g * 2 + 1][1]);
            }
#pragma unroll
            for (int nb = 0; nb < 8; ++nb) {
                mma16816(acc[nb][0], acc[nb][1], acc[nb][2], acc[nb][3],
                         aPH[0], aPH[1], aPH[2], aPH[3], bH[nb][0], bH[nb][1]);
                mma16816(acc[nb][0], acc[nb][1], acc[nb][2], acc[nb][3],
                         aPL[0], aPL[1], aPL[2], aPL[3], bH[nb][0], bH[nb][1]);
                mma16816(acc[nb][0], acc[nb][1], acc[nb][2], acc[nb][3],
                         aPH[0], aPH[1], aPH[2], aPH[3], bL[nb][0], bL[nb][1]);
            }
        }
    }

#pragma unroll
    for (int nb = 0; nb < 8; ++nb) {
        int col = h * HEAD_DIM + nb * 8 + ec;
        size_t r0 = (size_t)(b * T_SEQ + grow0) * K3 + col;
        size_t r1 = (size_t)(b * T_SEQ + grow0 + 8) * K3 + col;
        uint32_t hw, lw;
        bsplit2(acc[nb][0], acc[nb][1], hw, lw);
        *(uint32_t*)&zs[r0]        = hw;
        *(uint32_t*)&zs[r0 + 1024] = lw;
        *(uint32_t*)&zs[r0 + 2048] = hw;
        bsplit2(acc[nb][2], acc[nb][3], hw, lw);
        *(uint32_t*)&zs[r1]        = hw;
        *(uint32_t*)&zs[r1 + 1024] = lw;
        *(uint32_t*)&zs[r1 + 2048] = hw;
    }
}

// ---------------- launch ----------------------------------------------------
extern "C" void kernel_launch(void* const* d_in, const int* in_sizes, int n_in,
                              void* d_out, int out_size) {
    const float* x     = (const float*)d_in[0];
    const float* Wq    = (const float*)d_in[1];
    const float* Wk    = (const float*)d_in[2];
    const float* Wq2   = (const float*)d_in[3];
    const float* Wk2   = (const float*)d_in[4];
    const float* Wv    = (const float*)d_in[5];
    const float* Wproj = (const float*)d_in[6];

    float2* rtab;
    __nv_bfloat16 *xs, *zs, *wqs, *wks, *wq2s, *wk2s, *wvs, *wps;
    __nv_bfloat16 *qh, *ql, *q2h, *q2l, *kh, *kl, *k2h, *k2l, *vh, *vl;
    cudaGetSymbolAddress((void**)&rtab, g_rope);
    cudaGetSymbolAddress((void**)&xs,   g_xs);
    cudaGetSymbolAddress((void**)&zs,   g_zs);
    cudaGetSymbolAddress((void**)&wqs,  g_wqs);
    cudaGetSymbolAddress((void**)&wks,  g_wks);
    cudaGetSymbolAddress((void**)&wq2s, g_wq2s);
    cudaGetSymbolAddress((void**)&wk2s, g_wk2s);
    cudaGetSymbolAddress((void**)&wvs,  g_wvs);
    cudaGetSymbolAddress((void**)&wps,  g_wps);
    cudaGetSymbolAddress((void**)&qh,   g_qh);
    cudaGetSymbolAddress((void**)&ql,   g_ql);
    cudaGetSymbolAddress((void**)&q2h,  g_q2h);
    cudaGetSymbolAddress((void**)&q2l,  g_q2l);
    cudaGetSymbolAddress((void**)&kh,   g_kh);
    cudaGetSymbolAddress((void**)&kl,   g_kl);
    cudaGetSymbolAddress((void**)&k2h,  g_k2h);
    cudaGetSymbolAddress((void**)&k2l,  g_k2l);
    cudaGetSymbolAddress((void**)&vh,   g_vh);
    cudaGetSymbolAddress((void**)&vl,   g_vl);

    const int n4x = M_ROWS * D_MODEL / 4;
    const int n4w = D_MODEL * D_MODEL / 4;
    rope_table_kernel<<<(T_SEQ * 32) / 256, 256>>>(rtab);
    split_kernel<<<n4x / 256, 256>>>(x, xs, n4x, 0);
    split_w6<<<dim3(n4w / 256, 6), 256>>>(Wq, Wk, Wq2, Wk2, Wv, Wproj,
                                          wqs, wks, wq2s, wk2s, wvs, wps, n4w);

    cudaFuncSetAttribute(gemm_hmma,  cudaFuncAttributeMaxDynamicSharedMemorySize, GEMM_SMEM);
    cudaFuncSetAttribute(gemm_hmma5, cudaFuncAttributeMaxDynamicSharedMemorySize, GEMM_SMEM);
    dim3 gg5(D_MODEL / 128, M_ROWS / 128, 5);
    gemm_hmma5<<<gg5, 256, GEMM_SMEM>>>(xs, wqs, wks, wq2s, wk2s, wvs, rtab,
                                        qh, ql, kh, kl, q2h, q2l, k2h, k2l,
                                        vh, vl);

    cudaFuncSetAttribute(attn_hmma, cudaFuncAttributeMaxDynamicSharedMemorySize, AT_SMEM);
    attn_hmma<<<dim3(T_SEQ / 128, N_HEAD, B_SZ), 256, AT_SMEM>>>(
        qh, ql, q2h, q2l, kh, kl, k2h, k2l, vh, vl, zs);

    dim3 gg(D_MODEL / 128, M_ROWS / 128);
    gemm_hmma<<<gg, 256, GEMM_SMEM>>>(zs, wps, (float*)d_out);
}

// round 15
// speedup vs baseline: 1.0271x; 1.0271x over previous
#include <cuda_runtime.h>
#include <cuda_bf16.h>
#include <math.h>
#include <stdint.h>

#define D_MODEL  1024
#define N_HEAD   16
#define HEAD_DIM 64
#define B_SZ     2
#define T_SEQ    2048
#define M_ROWS   (B_SZ * T_SEQ)   // 4096
#define K3       3072             // split K: 3 terms of 1024

// ---------------- scratch (device globals: allocation-free) ----------------
__device__ float g_q [M_ROWS * D_MODEL];
__device__ float g_k [M_ROWS * D_MODEL];
__device__ float g_q2[M_ROWS * D_MODEL];
__device__ float g_k2[M_ROWS * D_MODEL];
__device__ float g_v [M_ROWS * D_MODEL];

// rope cos/sin table: [t][d] for t<2048, d<32
__device__ float2 g_rope[T_SEQ * 32];

// GEMM split buffers (K'=3072)
__device__ __nv_bfloat16 g_xs  [M_ROWS * K3];
__device__ __nv_bfloat16 g_zs  [M_ROWS * K3];   // written directly by attn
__device__ __nv_bfloat16 g_wqs [D_MODEL * K3];
__device__ __nv_bfloat16 g_wks [D_MODEL * K3];
__device__ __nv_bfloat16 g_wq2s[D_MODEL * K3];
__device__ __nv_bfloat16 g_wk2s[D_MODEL * K3];
__device__ __nv_bfloat16 g_wvs [D_MODEL * K3];
__device__ __nv_bfloat16 g_wps [D_MODEL * K3];

// attention split buffers (post-rope), layout [b*T, 1024]
__device__ __nv_bfloat16 g_qh [M_ROWS * D_MODEL];
__device__ __nv_bfloat16 g_ql [M_ROWS * D_MODEL];
__device__ __nv_bfloat16 g_q2h[M_ROWS * D_MODEL];
__device__ __nv_bfloat16 g_q2l[M_ROWS * D_MODEL];
__device__ __nv_bfloat16 g_kh [M_ROWS * D_MODEL];
__device__ __nv_bfloat16 g_kl [M_ROWS * D_MODEL];
__device__ __nv_bfloat16 g_k2h[M_ROWS * D_MODEL];
__device__ __nv_bfloat16 g_k2l[M_ROWS * D_MODEL];
// V transposed split: [b, h, d, t]
__device__ __nv_bfloat16 g_vh [B_SZ * N_HEAD * HEAD_DIM * T_SEQ];
__device__ __nv_bfloat16 g_vl [B_SZ * N_HEAD * HEAD_DIM * T_SEQ];

// ======================= helpers ===========================================
__device__ __forceinline__ uint32_t smem_u32(const void* p) {
    uint32_t a;
    asm("{ .reg .u64 t; cvta.to.shared.u64 t, %1; cvt.u32.u64 %0, t; }"
        : "=r"(a) : "l"(p));
    return a;
}
#define SWZ(off) ((off) ^ (((off) >> 3) & 0x70))

__device__ __forceinline__ void ldsm_x4(uint32_t addr, uint32_t& r0, uint32_t& r1,
                                        uint32_t& r2, uint32_t& r3) {
    asm volatile("ldmatrix.sync.aligned.m8n8.x4.shared.b16 {%0,%1,%2,%3}, [%4];"
                 : "=r"(r0), "=r"(r1), "=r"(r2), "=r"(r3) : "r"(addr));
}
__device__ __forceinline__ void mma16816(float& d0, float& d1, float& d2, float& d3,
                                         uint32_t a0, uint32_t a1, uint32_t a2, uint32_t a3,
                                         uint32_t b0, uint32_t b1) {
    asm volatile(
        "mma.sync.aligned.m16n8k16.row.col.f32.bf16.bf16.f32 "
        "{%0,%1,%2,%3}, {%4,%5,%6,%7}, {%8,%9}, {%0,%1,%2,%3};"
        : "+f"(d0), "+f"(d1), "+f"(d2), "+f"(d3)
        : "r"(a0), "r"(a1), "r"(a2), "r"(a3), "r"(b0), "r"(b1));
}
__device__ __forceinline__ void bsplit(float x, unsigned short& h, unsigned short& lo) {
    __nv_bfloat16 hh = __float2bfloat16(x);
    __nv_bfloat16 ll = __float2bfloat16(x - __bfloat162float(hh));
    h  = __bfloat16_as_ushort(hh);
    lo = __bfloat16_as_ushort(ll);
}
__device__ __forceinline__ void bsplit2(float x0, float x1, uint32_t& hw, uint32_t& lw) {
    unsigned short h0, l0, h1, l1;
    bsplit(x0, h0, l0);
    bsplit(x1, h1, l1);
    hw = (uint32_t)h0 | ((uint32_t)h1 << 16);
    lw = (uint32_t)l0 | ((uint32_t)l1 << 16);
}
#define CPA16(dst, src) \
    asm volatile("cp.async.cg.shared.global [%0], [%1], 16;" :: "r"(dst), "l"(src))
#define CPA_COMMIT() asm volatile("cp.async.commit_group;" ::: "memory")
#define CPA_WAIT0()  asm volatile("cp.async.wait_group 0;" ::: "memory")

// ======================= split fp32 -> bf16 3-term =========================
__device__ __forceinline__ void split_body(const float* __restrict__ X,
                                           __nv_bfloat16* __restrict__ S,
                                           int idx, int mode) {
    float4 v = ((const float4*)X)[idx];
    int r  = idx >> 8;
    int cq = (idx & 255) * 4;
    float vv[4] = {v.x, v.y, v.z, v.w};
    __nv_bfloat16 h[4], l[4];
#pragma unroll
    for (int j = 0; j < 4; j++) {
        h[j] = __float2bfloat16(vv[j]);
        l[j] = __float2bfloat16(vv[j] - __bfloat162float(h[j]));
    }
    size_t base = (size_t)r * K3 + cq;
    uint64_t hw = *(uint64_t*)h, lw = *(uint64_t*)l;
    *(uint64_t*)&S[base] = hw;
    if (mode == 0) {                       // A: hi, lo, hi
        *(uint64_t*)&S[base + 1024] = lw;
        *(uint64_t*)&S[base + 2048] = hw;
    } else {                               // W: hi, hi, lo
        *(uint64_t*)&S[base + 1024] = hw;
        *(uint64_t*)&S[base + 2048] = lw;
    }
}

__global__ void split_kernel(const float* __restrict__ X,
                             __nv_bfloat16* __restrict__ S, int n4, int mode) {
    int idx = blockIdx.x * blockDim.x + threadIdx.x;
    if (idx >= n4) return;
    split_body(X, S, idx, mode);
}

__global__ void split_w6(const float* __restrict__ W0, const float* __restrict__ W1,
                         const float* __restrict__ W2, const float* __restrict__ W3,
                         const float* __restrict__ W4, const float* __restrict__ W5,
                         __nv_bfloat16* __restrict__ S0, __nv_bfloat16* __restrict__ S1,
                         __nv_bfloat16* __restrict__ S2, __nv_bfloat16* __restrict__ S3,
                         __nv_bfloat16* __restrict__ S4, __nv_bfloat16* __restrict__ S5,
                         int n4) {
    int idx = blockIdx.x * blockDim.x + threadIdx.x;
    if (idx >= n4) return;
    const float* Ws[6] = {W0, W1, W2, W3, W4, W5};
    __nv_bfloat16* Ss[6] = {S0, S1, S2, S3, S4, S5};
    split_body(Ws[blockIdx.y], Ss[blockIdx.y], idx, 1);
}

// ======================= HMMA GEMM core ====================================
// 4-stage pipeline, one barrier per chunk (proof in round-11 notes).
#define TILE_BYTES 16384
#define STAGE_BYTES (2 * TILE_BYTES)
#define NSTAGE 4
#define GEMM_SMEM (NSTAGE * STAGE_BYTES + 1024)   // 132 KB
#define NCHUNK (K3 / 64)                 // 48

__device__ __forceinline__ void gemm_load(const __nv_bfloat16* __restrict__ As,
                                          const __nv_bfloat16* __restrict__ Ws,
                                          int m0, int n0, int c, uint32_t stb, int tid)
{
#pragma unroll
    for (int it = 0; it < 8; ++it) {
        int op = tid + it * 256;
        int t  = op >> 10;
        int r  = (op >> 3) & 127;
        int s  = op & 7;
        const __nv_bfloat16* g =
            (t ? Ws + (size_t)(n0 + r) * K3 : As + (size_t)(m0 + r) * K3)
            + c * 64 + s * 8;
        uint32_t d = stb + t * TILE_BYTES + SWZ(r * 128 + s * 16);
        CPA16(d, g);
    }
}

__device__ __forceinline__ void gemm_body(const __nv_bfloat16* __restrict__ As,
                                          const __nv_bfloat16* __restrict__ Ws,
                                          float* __restrict__ C,
                                          char* smem_raw)
{
    uint32_t sb = (smem_u32(smem_raw) + 1023u) & ~1023u;

    const int tid = threadIdx.x;
    const int wid = tid >> 5;
    const int l   = tid & 31;
    const int mw  = wid >> 2;
    const int nw  = wid & 3;
    const int m0  = blockIdx.y * 128;
    const int n0  = blockIdx.x * 128;

    float acc[4][4][4];
#pragma unroll
    for (int i = 0; i < 4; i++)
#pragma unroll
        for (int j = 0; j < 4; j++)
#pragma unroll
            for (int e = 0; e < 4; e++) acc[i][j][e] = 0.0f;

    const int a_row = mw * 64 + (l & 15);
    const int a_byt = (l >> 4) << 4;
    const int b_row = nw * 32 + ((l >> 4) << 3) + (l & 7);
    const int b_byt = ((l >> 3) & 1) << 4;

    gemm_load(As, Ws, m0, n0, 0, sb, tid);
    CPA_COMMIT();
    gemm_load(As, Ws, m0, n0, 1, sb + STAGE_BYTES, tid);
    CPA_COMMIT();

    for (int c = 0; c < NCHUNK; ++c) {
        if (c + 2 < NCHUNK) {
            gemm_load(As, Ws, m0, n0, c + 2, sb + ((c + 2) % NSTAGE) * STAGE_BYTES, tid);
            CPA_COMMIT();
            asm volatile("cp.async.wait_group 2;" ::: "memory");
        } else if (c + 2 == NCHUNK) {
            asm volatile("cp.async.wait_group 1;" ::: "memory");
        } else {
            CPA_WAIT0();
        }
        __syncthreads();

        const uint32_t aT = sb + (c % NSTAGE) * STAGE_BYTES;
        const uint32_t bT = aT + TILE_BYTES;

#pragma unroll
        for (int ks = 0; ks < 4; ++ks) {
            uint32_t a[4][4], b[4][2];
#pragma unroll
            for (int mi = 0; mi < 4; ++mi) {
                uint32_t ad = aT + SWZ((a_row + mi * 16) * 128 + ks * 32 + a_byt);
                ldsm_x4(ad, a[mi][0], a[mi][1], a[mi][2], a[mi][3]);
            }
#pragma unroll
            for (int nb = 0; nb < 2; ++nb) {
                uint32_t bd = bT + SWZ((b_row + nb * 16) * 128 + ks * 32 + b_byt);
                ldsm_x4(bd, b[nb * 2][0], b[nb * 2][1], b[nb * 2 + 1][0], b[nb * 2 + 1][1]);
            }
#pragma unroll
            for (int mi = 0; mi < 4; ++mi)
#pragma unroll
                for (int nj = 0; nj < 4; ++nj)
                    mma16816(acc[mi][nj][0], acc[mi][nj][1], acc[mi][nj][2], acc[mi][nj][3],
                             a[mi][0], a[mi][1], a[mi][2], a[mi][3],
                             b[nj][0], b[nj][1]);
        }
    }

    const int er = l >> 2;
    const int ec = (l & 3) * 2;
#pragma unroll
    for (int mi = 0; mi < 4; ++mi) {
        int mrow = m0 + mw * 64 + mi * 16 + er;
#pragma unroll
        for (int nj = 0; nj < 4; ++nj) {
            int ncol = n0 + nw * 32 + nj * 8 + ec;
            *(float2*)&C[(size_t)mrow * 1024 + ncol] =
                make_float2(acc[mi][nj][0], acc[mi][nj][1]);
            *(float2*)&C[(size_t)(mrow + 8) * 1024 + ncol] =
                make_float2(acc[mi][nj][2], acc[mi][nj][3]);
        }
    }
}

__global__ void __launch_bounds__(256) gemm_hmma(
    const __nv_bfloat16* __restrict__ As,
    const __nv_bfloat16* __restrict__ Ws,
    float* __restrict__ C)
{
    extern __shared__ char gsm_raw[];
    gemm_body(As, Ws, C, gsm_raw);
}

__global__ void __launch_bounds__(256) gemm_hmma5(
    const __nv_bfloat16* __restrict__ As,
    const __nv_bfloat16* __restrict__ W0, const __nv_bfloat16* __restrict__ W1,
    const __nv_bfloat16* __restrict__ W2, const __nv_bfloat16* __restrict__ W3,
    const __nv_bfloat16* __restrict__ W4,
    float* __restrict__ C0, float* __restrict__ C1, float* __restrict__ C2,
    float* __restrict__ C3, float* __restrict__ C4)
{
    extern __shared__ char gsm_raw[];
    const __nv_bfloat16* Ws[5] = {W0, W1, W2, W3, W4};
    float* Cs[5] = {C0, C1, C2, C3, C4};
    int zi = blockIdx.z;
    gemm_body(As, Ws[zi], Cs[zi], gsm_raw);
}

// ---------------- rope table: 65536 threads, double trig once --------------
__global__ void rope_table_kernel(float2* __restrict__ tab) {
    int idx = blockIdx.x * blockDim.x + threadIdx.x;   // t*32 + d
    if (idx >= T_SEQ * 32) return;
    int t = idx >> 5;
    int d = idx & 31;
    double inv = exp(-(double)d * 0.28782313662425572);   // ln(10000)/32
    double ang = (double)t * inv;
    tab[idx] = make_float2((float)cos(ang), (float)sin(ang));
}

// ---------------- RoPE -> split bf16 hi/lo (table-driven) ------------------
__global__ void rope_split_kernel(
    const float* __restrict__ q,  const float* __restrict__ k,
    const float* __restrict__ q2, const float* __restrict__ k2,
    const float2* __restrict__ tab,
    __nv_bfloat16* __restrict__ qh,  __nv_bfloat16* __restrict__ ql,
    __nv_bfloat16* __restrict__ q2h, __nv_bfloat16* __restrict__ q2l,
    __nv_bfloat16* __restrict__ kh,  __nv_bfloat16* __restrict__ kl,
    __nv_bfloat16* __restrict__ k2h, __nv_bfloat16* __restrict__ k2l)
{
    const int total = M_ROWS * N_HEAD * (HEAD_DIM / 2);
    int idx = blockIdx.x * blockDim.x + threadIdx.x;
    if (idx >= total) return;
    int m = idx >> 9;
    int r = idx & 511;
    int h = r >> 5;
    int d = r & 31;
    int t = m & (T_SEQ - 1);

    float2 cs = tab[t * 32 + d];
    float c = cs.x, s = cs.y;

    int base = m * D_MODEL + h * HEAD_DIM + d;
    const float* in[4]  = {q, k, q2, k2};
    __nv_bfloat16* oh[4] = {qh, kh, q2h, k2h};
    __nv_bfloat16* ol[4] = {ql, kl, q2l, k2l};
#pragma unroll
    for (int p = 0; p < 4; p++) {
        float x1 = in[p][base];
        float x2 = in[p][base + 32];
        float y1 =  x1 * c + x2 * s;
        float y2 = -x1 * s + x2 * c;
        unsigned short h1, l1, h2_, l2;
        bsplit(y1, h1, l1);
        bsplit(y2, h2_, l2);
        oh[p][base]      = __ushort_as_bfloat16(h1);
        ol[p][base]      = __ushort_as_bfloat16(l1);
        oh[p][base + 32] = __ushort_as_bfloat16(h2_);
        ol[p][base + 32] = __ushort_as_bfloat16(l2);
    }
}

// ---------------- V transpose + split: [b,t,h,d] f32 -> [b,h,d,t] bf16 -----
__global__ void vsplit_kernel(const float* __restrict__ v,
                              __nv_bfloat16* __restrict__ vh,
                              __nv_bfloat16* __restrict__ vl)
{
    __shared__ float ts[64][65];
    const int t0 = blockIdx.x * 64;
    const int h  = blockIdx.y;
    const int b  = blockIdx.z;
    const int tid = threadIdx.x;

    for (int e = tid; e < 4096; e += 256) {
        int t = e >> 6, d = e & 63;
        ts[t][d] = v[((size_t)(b * T_SEQ + t0 + t)) * D_MODEL + h * HEAD_DIM + d];
    }
    __syncthreads();
    for (int e = tid; e < 4096; e += 256) {
        int d = e >> 6, t = e & 63;
        float x = ts[t][d];
        unsigned short hh, ll;
        bsplit(x, hh, ll);
        size_t o = ((size_t)((b * N_HEAD + h) * HEAD_DIM + d)) * T_SEQ + t0 + t;
        vh[o] = __ushort_as_bfloat16(hh);
        vl[o] = __ushort_as_bfloat16(ll);
    }
}

// ---------------- HMMA flash-style attention (register repack) -------------
// 3-stage K/V pipeline, ONE barrier per kt:
//   iter kt: issue load(kt+1) into stage (kt+1)%3 -> wait_group 1 -> sync -> compute(kt)
// Overwrite safety: stage (kt+1)%3 last read at compute(kt-2); all warps
// passed sync(kt-1) only after finishing compute(kt-2).  Visibility: load(kt)
// was issued at iter kt-1; wait_group 1 at iter kt retires it; sync publishes.
#define AQ_TILE 16384
#define ST_BASE 65536
#define ST_SIZE 49152
#define ST_VOFF 32768
#define AT_NST  3
#define AT_SMEM (ST_BASE + AT_NST * ST_SIZE)   // 212992

__device__ __forceinline__ void attn_load_kv(
    const __nv_bfloat16* __restrict__ kh,  const __nv_bfloat16* __restrict__ kl,
    const __nv_bfloat16* __restrict__ k2h, const __nv_bfloat16* __restrict__ k2l,
    const __nv_bfloat16* __restrict__ vh,  const __nv_bfloat16* __restrict__ vl,
    int b, int h, int kt, uint32_t stb, int tid)
{
    const __nv_bfloat16* ksrc[4] = {kh, kl, k2h, k2l};
#pragma unroll
    for (int it = 0; it < 8; ++it) {
        int op = tid + it * 256;
        int arr = op >> 9;
        int r   = (op >> 3) & 63;
        int s   = op & 7;
        const __nv_bfloat16* g =
            ksrc[arr] + ((size_t)(b * T_SEQ + kt * 64 + r)) * D_MODEL + h * HEAD_DIM + s * 8;
        CPA16(stb + arr * 8192 + SWZ(r * 128 + s * 16), g);
    }
#pragma unroll
    for (int it = 0; it < 4; ++it) {
        int op = tid + it * 256;
        int arr = op >> 9;
        int r   = (op >> 3) & 63;
        int s   = op & 7;
        const __nv_bfloat16* g =
            (arr ? vl : vh)
            + ((size_t)((b * N_HEAD + h) * HEAD_DIM + r)) * T_SEQ + kt * 64 + s * 8;
        CPA16(stb + ST_VOFF + arr * 8192 + SWZ(r * 128 + s * 16), g);
    }
}

__global__ void __launch_bounds__(256, 1) attn_hmma(
    const __nv_bfloat16* __restrict__ qh,  const __nv_bfloat16* __restrict__ ql,
    const __nv_bfloat16* __restrict__ q2h, const __nv_bfloat16* __restrict__ q2l,
    const __nv_bfloat16* __restrict__ kh,  const __nv_bfloat16* __restrict__ kl,
    const __nv_bfloat16* __restrict__ k2h, const __nv_bfloat16* __restrict__ k2l,
    const __nv_bfloat16* __restrict__ vh,  const __nv_bfloat16* __restrict__ vl,
    __nv_bfloat16* __restrict__ zs)
{
    extern __shared__ char atn_raw[];
    const uint32_t sb = smem_u32(atn_raw);

    const int qt = (int)gridDim.x - 1 - (int)blockIdx.x;   // heavy first
    const int h  = blockIdx.y;
    const int b  = blockIdx.z;
    const int tid = threadIdx.x;
    const int wid = tid >> 5;
    const int l   = tid & 31;

    const int qrow0 = qt * 128;

    const int a_row = wid * 16 + (l & 15);
    const int a_byt = (l >> 4) << 4;
    const int b_row = ((l >> 4) << 3) + (l & 7);
    const int b_byt = ((l >> 3) & 1) << 4;
    const int er = l >> 2;
    const int ec = (l & 3) * 2;
    const int grow0 = qrow0 + wid * 16 + er;

    // ---- Q tiles ----
    {
        const __nv_bfloat16* src[4] = {qh, ql, q2h, q2l};
#pragma unroll
        for (int it = 0; it < 16; ++it) {
            int op = tid + it * 256;
            int arr = op >> 10;
            int r   = (op >> 3) & 127;
            int s   = op & 7;
            const __nv_bfloat16* g =
                src[arr] + ((size_t)(b * T_SEQ + qrow0 + r)) * D_MODEL + h * HEAD_DIM + s * 8;
            CPA16(sb + arr * AQ_TILE + SWZ(r * 128 + s * 16), g);
        }
        CPA_COMMIT();
    }
    attn_load_kv(kh, kl, k2h, k2l, vh, vl, b, h, 0, sb + ST_BASE, tid);
    CPA_COMMIT();

    float acc[8][4];
#pragma unroll
    for (int i = 0; i < 8; i++)
#pragma unroll
        for (int e = 0; e < 4; e++) acc[i][e] = 0.0f;

    const float scl = 1.0f / 4096.0f;
    const int kt_max = 2 * qt + 1;

    for (int kt = 0; kt <= kt_max; ++kt) {
        const uint32_t stb = sb + ST_BASE + (kt % AT_NST) * ST_SIZE;

        if (kt < kt_max) {
            attn_load_kv(kh, kl, k2h, k2l, vh, vl, b, h, kt + 1,
                         sb + ST_BASE + ((kt + 1) % AT_NST) * ST_SIZE, tid);
            CPA_COMMIT();
            asm volatile("cp.async.wait_group 1;" ::: "memory");
        } else {
            CPA_WAIT0();
        }
        __syncthreads();

        if (kt * 64 > qrow0 + wid * 16 + 15) continue;

        const uint32_t KH = stb, KL = stb + 8192, K2H = stb + 16384, K2L = stb + 24576;
        const uint32_t VH = stb + ST_VOFF, VL = stb + ST_VOFF + 8192;

        float s1[8][4], s2[8][4];
#pragma unroll
        for (int i = 0; i < 8; i++)
#pragma unroll
            for (int e = 0; e < 4; e++) { s1[i][e] = 0.0f; s2[i][e] = 0.0f; }

#pragma unroll
        for (int ks = 0; ks < 4; ++ks) {
            uint32_t aH[4], aL[4], bH[8][2], bL[8][2];
            ldsm_x4(sb + 0 * AQ_TILE + SWZ(a_row * 128 + ks * 32 + a_byt), aH[0], aH[1], aH[2], aH[3]);
            ldsm_x4(sb + 1 * AQ_TILE + SWZ(a_row * 128 + ks * 32 + a_byt), aL[0], aL[1], aL[2], aL[3]);
#pragma unroll
            for (int g = 0; g < 4; ++g) {
                ldsm_x4(KH + SWZ((b_row + g * 16) * 128 + ks * 32 + b_byt),
                        bH[g * 2][0], bH[g * 2][1], bH[g * 2 + 1][0], bH[g * 2 + 1][1]);
                ldsm_x4(KL + SWZ((b_row + g * 16) * 128 + ks * 32 + b_byt),
                        bL[g * 2][0], bL[g * 2][1], bL[g * 2 + 1][0], bL[g * 2 + 1][1]);
            }
#pragma unroll
            for (int nb = 0; nb < 8; ++nb) {
                mma16816(s1[nb][0], s1[nb][1], s1[nb][2], s1[nb][3],
                         aH[0], aH[1], aH[2], aH[3], bH[nb][0], bH[nb][1]);
                mma16816(s1[nb][0], s1[nb][1], s1[nb][2], s1[nb][3],
                         aL[0], aL[1], aL[2], aL[3], bH[nb][0], bH[nb][1]);
                mma16816(s1[nb][0], s1[nb][1], s1[nb][2], s1[nb][3],
                         aH[0], aH[1], aH[2], aH[3], bL[nb][0], bL[nb][1]);
            }
        }
#pragma unroll
        for (int ks = 0; ks < 4; ++ks) {
            uint32_t aH[4], aL[4], bH[8][2], bL[8][2];
            ldsm_x4(sb + 2 * AQ_TILE + SWZ(a_row * 128 + ks * 32 + a_byt), aH[0], aH[1], aH[2], aH[3]);
            ldsm_x4(sb + 3 * AQ_TILE + SWZ(a_row * 128 + ks * 32 + a_byt), aL[0], aL[1], aL[2], aL[3]);
#pragma unroll
            for (int g = 0; g < 4; ++g) {
                ldsm_x4(K2H + SWZ((b_row + g * 16) * 128 + ks * 32 + b_byt),
                        bH[g * 2][0], bH[g * 2][1], bH[g * 2 + 1][0], bH[g * 2 + 1][1]);
                ldsm_x4(K2L + SWZ((b_row + g * 16) * 128 + ks * 32 + b_byt),
                        bL[g * 2][0], bL[g * 2][1], bL[g * 2 + 1][0], bL[g * 2 + 1][1]);
            }
#pragma unroll
            for (int nb = 0; nb < 8; ++nb) {
                mma16816(s2[nb][0], s2[nb][1], s2[nb][2], s2[nb][3],
                         aH[0], aH[1], aH[2], aH[3], bH[nb][0], bH[nb][1]);
                mma16816(s2[nb][0], s2[nb][1], s2[nb][2], s2[nb][3],
                         aL[0], aL[1], aL[2], aL[3], bH[nb][0], bH[nb][1]);
                mma16816(s2[nb][0], s2[nb][1], s2[nb][2], s2[nb][3],
                         aH[0], aH[1], aH[2], aH[3], bL[nb][0], bL[nb][1]);
            }
        }

        const bool maskt = (kt >= 2 * qt);
        uint32_t pH[8], pL[8], pH2[8], pL2[8];
#pragma unroll
        for (int nb = 0; nb < 8; ++nb) {
            float p0 = s1[nb][0] * s2[nb][0] * scl;
            float p1 = s1[nb][1] * s2[nb][1] * scl;
            float p2 = s1[nb][2] * s2[nb][2] * scl;
            float p3 = s1[nb][3] * s2[nb][3] * scl;
            if (maskt) {
                int c0 = kt * 64 + nb * 8 + ec;
                if (c0     > grow0    ) p0 = 0.0f;
                if (c0 + 1 > grow0    ) p1 = 0.0f;
                if (c0     > grow0 + 8) p2 = 0.0f;
                if (c0 + 1 > grow0 + 8) p3 = 0.0f;
            }
            bsplit2(p0, p1, pH[nb],  pL[nb]);
            bsplit2(p2, p3, pH2[nb], pL2[nb]);
        }

#pragma unroll
        for (int kc = 0; kc < 4; ++kc) {
            uint32_t aPH[4] = {pH[2 * kc], pH2[2 * kc], pH[2 * kc + 1], pH2[2 * kc + 1]};
            uint32_t aPL[4] = {pL[2 * kc], pL2[2 * kc], pL[2 * kc + 1], pL2[2 * kc + 1]};
            uint32_t bH[8][2], bL[8][2];
#pragma unroll
            for (int g = 0; g < 4; ++g) {
                ldsm_x4(VH + SWZ((b_row + g * 16) * 128 + kc * 32 + b_byt),
                        bH[g * 2][0], bH[g * 2][1], bH[g * 2 + 1][0], bH[g * 2 + 1][1]);
                ldsm_x4(VL + SWZ((b_row + g * 16) * 128 + kc * 32 + b_byt),
                        bL[g * 2][0], bL[g * 2][1], bL[g * 2 + 1][0], bL[g * 2 + 1][1]);
            }
#pragma unroll
            for (int nb = 0; nb < 8; ++nb) {
                mma16816(acc[nb][0], acc[nb][1], acc[nb][2], acc[nb][3],
                         aPH[0], aPH[1], aPH[2], aPH[3], bH[nb][0], bH[nb][1]);
                mma16816(acc[nb][0], acc[nb][1], acc[nb][2], acc[nb][3],
                         aPL[0], aPL[1], aPL[2], aPL[3], bH[nb][0], bH[nb][1]);
                mma16816(acc[nb][0], acc[nb][1], acc[nb][2], acc[nb][3],
                         aPH[0], aPH[1], aPH[2], aPH[3], bL[nb][0], bL[nb][1]);
            }
        }
    }

#pragma unroll
    for (int nb = 0; nb < 8; ++nb) {
        int col = h * HEAD_DIM + nb * 8 + ec;
        size_t r0 = (size_t)(b * T_SEQ + grow0) * K3 + col;
        size_t r1 = (size_t)(b * T_SEQ + grow0 + 8) * K3 + col;
        uint32_t hw, lw;
        bsplit2(acc[nb][0], acc[nb][1], hw, lw);
        *(uint32_t*)&zs[r0]        = hw;
        *(uint32_t*)&zs[r0 + 1024] = lw;
        *(uint32_t*)&zs[r0 + 2048] = hw;
        bsplit2(acc[nb][2], acc[nb][3], hw, lw);
        *(uint32_t*)&zs[r1]        = hw;
        *(uint32_t*)&zs[r1 + 1024] = lw;
        *(uint32_t*)&zs[r1 + 2048] = hw;
    }
}

// ---------------- launch ----------------------------------------------------
extern "C" void kernel_launch(void* const* d_in, const int* in_sizes, int n_in,
                              void* d_out, int out_size) {
    const float* x     = (const float*)d_in[0];
    const float* Wq    = (const float*)d_in[1];
    const float* Wk    = (const float*)d_in[2];
    const float* Wq2   = (const float*)d_in[3];
    const float* Wk2   = (const float*)d_in[4];
    const float* Wv    = (const float*)d_in[5];
    const float* Wproj = (const float*)d_in[6];

    float *q, *k, *q2, *k2, *v;
    float2* rtab;
    __nv_bfloat16 *xs, *zs, *wqs, *wks, *wq2s, *wk2s, *wvs, *wps;
    __nv_bfloat16 *qh, *ql, *q2h, *q2l, *kh, *kl, *k2h, *k2l, *vh, *vl;
    cudaGetSymbolAddress((void**)&q,    g_q);
    cudaGetSymbolAddress((void**)&k,    g_k);
    cudaGetSymbolAddress((void**)&q2,   g_q2);
    cudaGetSymbolAddress((void**)&k2,   g_k2);
    cudaGetSymbolAddress((void**)&v,    g_v);
    cudaGetSymbolAddress((void**)&rtab, g_rope);
    cudaGetSymbolAddress((void**)&xs,   g_xs);
    cudaGetSymbolAddress((void**)&zs,   g_zs);
    cudaGetSymbolAddress((void**)&wqs,  g_wqs);
    cudaGetSymbolAddress((void**)&wks,  g_wks);
    cudaGetSymbolAddress((void**)&wq2s, g_wq2s);
    cudaGetSymbolAddress((void**)&wk2s, g_wk2s);
    cudaGetSymbolAddress((void**)&wvs,  g_wvs);
    cudaGetSymbolAddress((void**)&wps,  g_wps);
    cudaGetSymbolAddress((void**)&qh,   g_qh);
    cudaGetSymbolAddress((void**)&ql,   g_ql);
    cudaGetSymbolAddress((void**)&q2h,  g_q2h);
    cudaGetSymbolAddress((void**)&q2l,  g_q2l);
    cudaGetSymbolAddress((void**)&kh,   g_kh);
    cudaGetSymbolAddress((void**)&kl,   g_kl);
    cudaGetSymbolAddress((void**)&k2h,  g_k2h);
    cudaGetSymbolAddress((void**)&k2l,  g_k2l);
    cudaGetSymbolAddress((void**)&vh,   g_vh);
    cudaGetSymbolAddress((void**)&vl,   g_vl);

    const int n4x = M_ROWS * D_MODEL / 4;
    const int n4w = D_MODEL * D_MODEL / 4;
    rope_table_kernel<<<(T_SEQ * 32) / 256, 256>>>(rtab);
    split_kernel<<<n4x / 256, 256>>>(x, xs, n4x, 0);
    split_w6<<<dim3(n4w / 256, 6), 256>>>(Wq, Wk, Wq2, Wk2, Wv, Wproj,
                                          wqs, wks, wq2s, wk2s, wvs, wps, n4w);

    cudaFuncSetAttribute(gemm_hmma,  cudaFuncAttributeMaxDynamicSharedMemorySize, GEMM_SMEM);
    cudaFuncSetAttribute(gemm_hmma5, cudaFuncAttributeMaxDynamicSharedMemorySize, GEMM_SMEM);
    dim3 gg5(D_MODEL / 128, M_ROWS / 128, 5);
    gemm_hmma5<<<gg5, 256, GEMM_SMEM>>>(xs, wqs, wks, wq2s, wk2s, wvs,
                                        q, k, q2, k2, v);

    int pairs = M_ROWS * N_HEAD * (HEAD_DIM / 2);
    rope_split_kernel<<<(pairs + 255) / 256, 256>>>(
        q, k, q2, k2, rtab, qh, ql, q2h, q2l, kh, kl, k2h, k2l);

    vsplit_kernel<<<dim3(T_SEQ / 64, N_HEAD, B_SZ), 256>>>(v, vh, vl);

    cudaFuncSetAttribute(attn_hmma, cudaFuncAttributeMaxDynamicSharedMemorySize, AT_SMEM);
    attn_hmma<<<dim3(T_SEQ / 128, N_HEAD, B_SZ), 256, AT_SMEM>>>(
        qh, ql, q2h, q2l, kh, kl, k2h, k2l, vh, vl, zs);

    dim3 gg(D_MODEL / 128, M_ROWS / 128);
    gemm_hmma<<<gg, 256, GEMM_SMEM>>>(zs, wps, (float*)d_out);
}